// round 4
// baseline (speedup 1.0000x reference)
#include <cuda_runtime.h>
#include <math.h>

#define NN 50000
#define EE 800000
#define NDIM 32
#define EDIM 16
#define HID 96
#define NHEAD 4
#define CPH 24

typedef unsigned long long ull;

#define FMA2(d, a, b, c) \
    asm("fma.rn.f32x2 %0, %1, %2, %3;" : "=l"(d) : "l"(a), "l"(b), "l"(c))
#define PACK2(out, lo, hi) \
    asm("mov.b64 %0, {%1, %2};" : "=l"(out) : "f"(lo), "f"(hi))
#define UNPACK2(lo, hi, in) \
    asm("mov.b64 {%0, %1}, %2;" : "=f"(lo), "=f"(hi) : "l"(in))

// ---------------- scratch (device globals; no runtime allocation) ----------
__device__ float  g_h[NN * HID];
__device__ float  g_xl[NN * HID];
__device__ float  g_xr[NN * HID];
__device__ int    g_rowptr[NN + 1];
__device__ int    g_cursor[NN];
__device__ int    g_eid[EE];
__device__ int    g_src_p[EE];          // src node id, CSR-permuted
__device__ float  g_eattr_p[EE * EDIM]; // edge attrs, CSR-permuted (51 MB)

// ---------------- CSR build ------------------------------------------------
__global__ void k_zero() {
    int i = blockIdx.x * blockDim.x + threadIdx.x;
    if (i <= NN) g_rowptr[i] = 0;
}

__global__ void k_count(const int* __restrict__ dst) {
    int e = blockIdx.x * blockDim.x + threadIdx.x;
    if (e < EE) atomicAdd(&g_rowptr[dst[e] + 1], 1);
}

// single-block scan, warp-scan hierarchy
__global__ void __launch_bounds__(1024) k_scan() {
    const int TOT = NN + 1;
    const int CH = (TOT + 1023) / 1024;  // 49
    int t = threadIdx.x;
    int b = t * CH;
    int vals[CH];
    int sum = 0;
#pragma unroll
    for (int j = 0; j < CH; j++) {
        int i = b + j;
        int v = (i < TOT) ? g_rowptr[i] : 0;
        vals[j] = v;
        sum += v;
    }
    int lane = t & 31, wid = t >> 5;
    int x = sum;
#pragma unroll
    for (int o = 1; o < 32; o <<= 1) {
        int y = __shfl_up_sync(0xffffffffu, x, o);
        if (lane >= o) x += y;
    }
    __shared__ int wsum[32];
    if (lane == 31) wsum[wid] = x;
    __syncthreads();
    if (wid == 0) {
        int w = wsum[lane];
#pragma unroll
        for (int o = 1; o < 32; o <<= 1) {
            int y = __shfl_up_sync(0xffffffffu, w, o);
            if (lane >= o) w += y;
        }
        wsum[lane] = w;
    }
    __syncthreads();
    int run = x - sum + (wid ? wsum[wid - 1] : 0);
#pragma unroll
    for (int j = 0; j < CH; j++) {
        int i = b + j;
        if (i < TOT) {
            run += vals[j];
            g_rowptr[i] = run;
            if (i < NN) g_cursor[i] = run;
        }
    }
}

__global__ void k_fill(const int* __restrict__ src, const int* __restrict__ dst) {
    int e = blockIdx.x * blockDim.x + threadIdx.x;
    if (e < EE) {
        int p = atomicAdd(&g_cursor[dst[e]], 1);
        g_eid[p] = e;
        g_src_p[p] = src[e];
    }
}

__global__ void k_perm(const float* __restrict__ eattr) {
    int i = blockIdx.x * blockDim.x + threadIdx.x;
    if (i < EE) {
        int e = g_eid[i];
        const float4* s = (const float4*)(eattr + e * EDIM);
        float4* d = (float4*)(g_eattr_p + (long)i * EDIM);
        d[0] = s[0]; d[1] = s[1]; d[2] = s[2]; d[3] = s[3];
    }
}

// ---------------- proj: out[N,96] = in[N,32] @ W + b (persistent) ----------
__global__ void __launch_bounds__(96) k_proj(const float* __restrict__ in,
                                             const float* __restrict__ W,
                                             const float* __restrict__ bias,
                                             float* __restrict__ out) {
    __shared__ float h_sh[16 * NDIM];
    int tid = threadIdx.x;
    float wreg[NDIM];
#pragma unroll
    for (int k = 0; k < NDIM; k++) wreg[k] = W[k * HID + tid];
    float bv = bias[tid];
    for (int n0 = blockIdx.x * 16; n0 < NN; n0 += gridDim.x * 16) {
        __syncthreads();
        for (int idx = tid; idx < 16 * NDIM; idx += 96) {
            int nn = n0 + idx / NDIM;
            h_sh[idx] = (nn < NN) ? in[n0 * NDIM + idx] : 0.f;
        }
        __syncthreads();
        float acc[16];
#pragma unroll
        for (int j = 0; j < 16; j++) acc[j] = bv;
#pragma unroll
        for (int k = 0; k < NDIM; k += 4) {
#pragma unroll
            for (int j = 0; j < 16; j++) {
                float4 hv = *(const float4*)&h_sh[j * NDIM + k];
                acc[j] = fmaf(hv.x, wreg[k + 0], acc[j]);
                acc[j] = fmaf(hv.y, wreg[k + 1], acc[j]);
                acc[j] = fmaf(hv.z, wreg[k + 2], acc[j]);
                acc[j] = fmaf(hv.w, wreg[k + 3], acc[j]);
            }
        }
#pragma unroll
        for (int j = 0; j < 16; j++)
            if (n0 + j < NN) out[(n0 + j) * HID + tid] = acc[j];
    }
}

// ---------------- fused lin_l + lin_r, packed f32x2 over K -----------------
__global__ void __launch_bounds__(192) k_lin2(const float* __restrict__ in,
                                              const float* __restrict__ Wl,
                                              const float* __restrict__ bl,
                                              const float* __restrict__ Wr,
                                              const float* __restrict__ br,
                                              float* __restrict__ outl,
                                              float* __restrict__ outr) {
    __shared__ float h_sh[16 * HID];
    int tid = threadIdx.x;
    int col = tid % 96;
    bool isR = tid >= 96;
    const float* W = isR ? Wr : Wl;
    ull wp[48];
#pragma unroll
    for (int kk = 0; kk < 48; kk++) {
        float lo = W[(2 * kk) * HID + col];
        float hi = W[(2 * kk + 1) * HID + col];
        PACK2(wp[kk], lo, hi);
    }
    float bv = isR ? br[col] : bl[col];
    float* out = isR ? outr : outl;

    for (int n0 = blockIdx.x * 16; n0 < NN; n0 += gridDim.x * 16) {
        __syncthreads();
        for (int idx = tid; idx < 16 * HID; idx += 192) {
            int nn = n0 + idx / HID;
            h_sh[idx] = (nn < NN) ? in[n0 * HID + idx] : 0.f;
        }
        __syncthreads();
        ull acc2[16];
#pragma unroll
        for (int j = 0; j < 16; j++) PACK2(acc2[j], bv, 0.f);
#pragma unroll
        for (int kq = 0; kq < 24; kq++) {
#pragma unroll
            for (int j = 0; j < 16; j++) {
                ulonglong2 hv = *(const ulonglong2*)&h_sh[j * HID + 4 * kq];
                FMA2(acc2[j], hv.x, wp[2 * kq], acc2[j]);
                FMA2(acc2[j], hv.y, wp[2 * kq + 1], acc2[j]);
            }
        }
#pragma unroll
        for (int j = 0; j < 16; j++) {
            if (n0 + j < NN) {
                float lo, hi;
                UNPACK2(lo, hi, acc2[j]);
                out[(n0 + j) * HID + col] = lo + hi;
            }
        }
    }
}

// ---------------- fused GATv2 layer (packed f32x2 edge-GEMM) ---------------
// Warp per node (persistent). Lane owns channels [3*lane, 3*lane+2],
// head = lane/8 (8 lanes per head). We column-pairs live in registers.
__global__ void __launch_bounds__(128) k_layer(const float* __restrict__ We,
                                               const float* __restrict__ att,
                                               const float* __restrict__ cb,
                                               const float* __restrict__ lng,
                                               const float* __restrict__ lnb) {
    int tid = threadIdx.x;
    int lane = tid & 31;
    int w = tid >> 5;
    int c = 3 * lane;

    // preload this lane's 3 We columns as K-pairs (24 packed regs)
    ull w0[8], w1[8], w2[8];
#pragma unroll
    for (int kk = 0; kk < 8; kk++) {
        PACK2(w0[kk], We[(2 * kk) * HID + c],     We[(2 * kk + 1) * HID + c]);
        PACK2(w1[kk], We[(2 * kk) * HID + c + 1], We[(2 * kk + 1) * HID + c + 1]);
        PACK2(w2[kk], We[(2 * kk) * HID + c + 2], We[(2 * kk + 1) * HID + c + 2]);
    }
    float at0 = att[c], at1 = att[c + 1], at2 = att[c + 2];
    float cb0 = cb[c], cb1 = cb[c + 1], cb2 = cb[c + 2];
    float lg0 = lng[c], lg1 = lng[c + 1], lg2 = lng[c + 2];
    float lb0 = lnb[c], lb1 = lnb[c + 1], lb2 = lnb[c + 2];

    for (int n = blockIdx.x * 4 + w; n < NN; n += gridDim.x * 4) {
        int r0 = g_rowptr[n], r1 = g_rowptr[n + 1];
        float xr0 = g_xr[n * HID + c];
        float xr1 = g_xr[n * HID + c + 1];
        float xr2 = g_xr[n * HID + c + 2];

        float mx = -3e38f, s = 0.f;
        float acc0 = 0.f, acc1 = 0.f, acc2v = 0.f;

        for (int i = r0; i < r1; i++) {
            int sidx = g_src_p[i];
            // edge attrs: 4 uniform 16B loads -> 8 packed f32x2 operands
            const ulonglong2* ep = (const ulonglong2*)(g_eattr_p + (long)i * EDIM);
            ulonglong2 ea0 = ep[0], ea1 = ep[1], ea2 = ep[2], ea3 = ep[3];
            ull a[8] = {ea0.x, ea0.y, ea1.x, ea1.y, ea2.x, ea2.y, ea3.x, ea3.y};
            const float* xlp = g_xl + sidx * HID;
            float xl0 = xlp[c], xl1 = xlp[c + 1], xl2 = xlp[c + 2];

            ull p0, p1, p2;
            PACK2(p0, 0.f, 0.f); PACK2(p1, 0.f, 0.f); PACK2(p2, 0.f, 0.f);
#pragma unroll
            for (int kk = 0; kk < 8; kk++) {
                FMA2(p0, a[kk], w0[kk], p0);
                FMA2(p1, a[kk], w1[kk], p1);
                FMA2(p2, a[kk], w2[kk], p2);
            }
            float e0l, e0h, e1l, e1h, e2l, e2h;
            UNPACK2(e0l, e0h, p0);
            UNPACK2(e1l, e1h, p1);
            UNPACK2(e2l, e2h, p2);
            float m0 = (e0l + e0h) + (xl0 + xr0);
            float m1 = (e1l + e1h) + (xl1 + xr1);
            float m2 = (e2l + e2h) + (xl2 + xr2);
            m0 = fmaxf(m0, 0.2f * m0);
            m1 = fmaxf(m1, 0.2f * m1);
            m2 = fmaxf(m2, 0.2f * m2);
            float v = m0 * at0 + m1 * at1 + m2 * at2;
            v += __shfl_xor_sync(0xffffffffu, v, 4);
            v += __shfl_xor_sync(0xffffffffu, v, 2);
            v += __shfl_xor_sync(0xffffffffu, v, 1);
            float nm = fmaxf(mx, v);
            float sc = __expf(mx - nm);
            float p  = __expf(v - nm);
            s = fmaf(s, sc, p);
            acc0  = fmaf(acc0, sc, p * xl0);
            acc1  = fmaf(acc1, sc, p * xl1);
            acc2v = fmaf(acc2v, sc, p * xl2);
            mx = nm;
        }
        float inv = 1.f / (s + 1e-16f);
        float h0 = g_h[n * HID + c]     + acc0  * inv + cb0;
        float h1 = g_h[n * HID + c + 1] + acc1  * inv + cb1;
        float h2 = g_h[n * HID + c + 2] + acc2v * inv + cb2;
        float sm = h0 + h1 + h2;
#pragma unroll
        for (int off = 16; off; off >>= 1) sm += __shfl_xor_sync(0xffffffffu, sm, off);
        float mu = sm * (1.f / 96.f);
        float d0 = h0 - mu, d1 = h1 - mu, d2 = h2 - mu;
        float vv = d0 * d0 + d1 * d1 + d2 * d2;
#pragma unroll
        for (int off = 16; off; off >>= 1) vv += __shfl_xor_sync(0xffffffffu, vv, off);
        float rs = rsqrtf(vv * (1.f / 96.f) + 1e-5f);
        g_h[n * HID + c]     = d0 * rs * lg0 + lb0;
        g_h[n * HID + c + 1] = d1 * rs * lg1 + lb1;
        g_h[n * HID + c + 2] = d2 * rs * lg2 + lb2;
    }
}

// ---------------- MLP head -------------------------------------------------
__global__ void __launch_bounds__(128) k_head(const float* __restrict__ w1,
                                              const float* __restrict__ b1,
                                              const float* __restrict__ w2,
                                              const float* __restrict__ b2,
                                              float* __restrict__ out) {
    __shared__ float w1s[HID * 48];
    __shared__ float b1s[48];
    __shared__ float w2s[48];
    int tid = threadIdx.x;
    for (int i = tid; i < HID * 48; i += 128) w1s[i] = w1[i];
    if (tid < 48) { b1s[tid] = b1[tid]; w2s[tid] = w2[tid]; }
    __syncthreads();
    int node = blockIdx.x * 128 + tid;
    if (node >= NN) return;

    float hreg[HID];
#pragma unroll
    for (int k = 0; k < HID; k += 4) {
        float4 v = *(const float4*)&g_h[node * HID + k];
        hreg[k] = v.x; hreg[k + 1] = v.y; hreg[k + 2] = v.z; hreg[k + 3] = v.w;
    }
    float y = 0.f;
#pragma unroll 2
    for (int j = 0; j < 48; j += 4) {
        float a0 = b1s[j], a1 = b1s[j + 1], a2 = b1s[j + 2], a3 = b1s[j + 3];
#pragma unroll
        for (int k = 0; k < HID; k++) {
            float4 wv = *(const float4*)&w1s[k * 48 + j];
            a0 = fmaf(hreg[k], wv.x, a0);
            a1 = fmaf(hreg[k], wv.y, a1);
            a2 = fmaf(hreg[k], wv.z, a2);
            a3 = fmaf(hreg[k], wv.w, a3);
        }
        float g0 = 0.5f * a0 * (1.f + erff(a0 * 0.70710678118654752f));
        float g1 = 0.5f * a1 * (1.f + erff(a1 * 0.70710678118654752f));
        float g2 = 0.5f * a2 * (1.f + erff(a2 * 0.70710678118654752f));
        float g3 = 0.5f * a3 * (1.f + erff(a3 * 0.70710678118654752f));
        y = fmaf(g0, w2s[j], y);
        y = fmaf(g1, w2s[j + 1], y);
        y = fmaf(g2, w2s[j + 2], y);
        y = fmaf(g3, w2s[j + 3], y);
    }
    out[node] = y + b2[0];
}

// ---------------- launch ---------------------------------------------------
extern "C" void kernel_launch(void* const* d_in, const int* in_sizes, int n_in,
                              void* d_out, int out_size) {
    const float* x      = (const float*)d_in[0];
    const int*   ei     = (const int*)d_in[1];
    const float* eattr  = (const float*)d_in[2];
    const float* proj_w = (const float*)d_in[3];
    const float* proj_b = (const float*)d_in[4];
    const float* ll_w   = (const float*)d_in[5];
    const float* ll_b   = (const float*)d_in[6];
    const float* lr_w   = (const float*)d_in[7];
    const float* lr_b   = (const float*)d_in[8];
    const float* le_w   = (const float*)d_in[9];
    const float* att    = (const float*)d_in[10];
    const float* cb     = (const float*)d_in[11];
    const float* lng    = (const float*)d_in[12];
    const float* lnb    = (const float*)d_in[13];
    const float* hw1    = (const float*)d_in[14];
    const float* hb1    = (const float*)d_in[15];
    const float* hw2    = (const float*)d_in[16];
    const float* hb2    = (const float*)d_in[17];
    float* out = (float*)d_out;

    const int* src = ei;
    const int* dst = ei + EE;

    float *ph, *pxl, *pxr;
    cudaGetSymbolAddress((void**)&ph,  g_h);
    cudaGetSymbolAddress((void**)&pxl, g_xl);
    cudaGetSymbolAddress((void**)&pxr, g_xr);

    // CSR build + edge permutation (once per call)
    k_zero<<<(NN + 256) / 256, 256>>>();
    k_count<<<(EE + 255) / 256, 256>>>(dst);
    k_scan<<<1, 1024>>>();
    k_fill<<<(EE + 255) / 256, 256>>>(src, dst);
    k_perm<<<(EE + 255) / 256, 256>>>(eattr);

    // input projection (persistent)
    k_proj<<<592, 96>>>(x, proj_w, proj_b, ph);

    for (int l = 0; l < 3; l++) {
        k_lin2<<<592, 192>>>(ph, ll_w + l * HID * HID, ll_b + l * HID,
                             lr_w + l * HID * HID, lr_b + l * HID, pxl, pxr);
        k_layer<<<1184, 128>>>(le_w + l * EDIM * HID, att + l * HID,
                               cb + l * HID, lng + l * HID, lnb + l * HID);
    }

    k_head<<<(NN + 127) / 128, 128>>>(hw1, hb1, hw2, hb2, out);
}

// round 5
// speedup vs baseline: 1.0610x; 1.0610x over previous
#include <cuda_runtime.h>
#include <math.h>

#define NN 50000
#define EE 800000
#define NDIM 32
#define EDIM 16
#define HID 96
#define NHEAD 4
#define CPH 24

typedef unsigned long long ull;

#define FMA2(d, a, b, c) \
    asm("fma.rn.f32x2 %0, %1, %2, %3;" : "=l"(d) : "l"(a), "l"(b), "l"(c))
#define PACK2(out, lo, hi) \
    asm("mov.b64 %0, {%1, %2};" : "=l"(out) : "f"(lo), "f"(hi))
#define UNPACK2(lo, hi, in) \
    asm("mov.b64 {%0, %1}, %2;" : "=f"(lo), "=f"(hi) : "l"(in))

// ---------------- scratch (device globals; no runtime allocation) ----------
__device__ float  g_h[NN * HID];
__device__ float  g_xl[NN * HID];
__device__ float  g_xr[NN * HID];
__device__ int    g_rowptr[NN + 1];
__device__ int    g_cursor[NN];
__device__ int    g_eid[EE];
__device__ int    g_src_p[EE];          // src node id, CSR-permuted
__device__ float  g_eattr_p[EE * EDIM]; // edge attrs, CSR-permuted (51 MB)

// ---------------- CSR build ------------------------------------------------
__global__ void k_zero() {
    int i = blockIdx.x * blockDim.x + threadIdx.x;
    if (i <= NN) g_rowptr[i] = 0;
}

__global__ void k_count(const int* __restrict__ dst) {
    int e = blockIdx.x * blockDim.x + threadIdx.x;
    if (e < EE) atomicAdd(&g_rowptr[dst[e] + 1], 1);
}

// single-block scan, warp-scan hierarchy
__global__ void __launch_bounds__(1024) k_scan() {
    const int TOT = NN + 1;
    const int CH = (TOT + 1023) / 1024;  // 49
    int t = threadIdx.x;
    int b = t * CH;
    int vals[CH];
    int sum = 0;
#pragma unroll
    for (int j = 0; j < CH; j++) {
        int i = b + j;
        int v = (i < TOT) ? g_rowptr[i] : 0;
        vals[j] = v;
        sum += v;
    }
    int lane = t & 31, wid = t >> 5;
    int x = sum;
#pragma unroll
    for (int o = 1; o < 32; o <<= 1) {
        int y = __shfl_up_sync(0xffffffffu, x, o);
        if (lane >= o) x += y;
    }
    __shared__ int wsum[32];
    if (lane == 31) wsum[wid] = x;
    __syncthreads();
    if (wid == 0) {
        int w = wsum[lane];
#pragma unroll
        for (int o = 1; o < 32; o <<= 1) {
            int y = __shfl_up_sync(0xffffffffu, w, o);
            if (lane >= o) w += y;
        }
        wsum[lane] = w;
    }
    __syncthreads();
    int run = x - sum + (wid ? wsum[wid - 1] : 0);
#pragma unroll
    for (int j = 0; j < CH; j++) {
        int i = b + j;
        if (i < TOT) {
            run += vals[j];
            g_rowptr[i] = run;
            if (i < NN) g_cursor[i] = run;
        }
    }
}

__global__ void k_fill(const int* __restrict__ src, const int* __restrict__ dst) {
    int e = blockIdx.x * blockDim.x + threadIdx.x;
    if (e < EE) {
        int p = atomicAdd(&g_cursor[dst[e]], 1);
        g_eid[p] = e;
        g_src_p[p] = src[e];
    }
}

__global__ void k_perm(const float* __restrict__ eattr) {
    int i = blockIdx.x * blockDim.x + threadIdx.x;
    if (i < EE) {
        int e = g_eid[i];
        const float4* s = (const float4*)(eattr + e * EDIM);
        float4* d = (float4*)(g_eattr_p + (long)i * EDIM);
        d[0] = s[0]; d[1] = s[1]; d[2] = s[2]; d[3] = s[3];
    }
}

// ---------------- proj: out[N,96] = in[N,32] @ W + b (persistent) ----------
__global__ void __launch_bounds__(96) k_proj(const float* __restrict__ in,
                                             const float* __restrict__ W,
                                             const float* __restrict__ bias,
                                             float* __restrict__ out) {
    __shared__ float h_sh[16 * NDIM];
    int tid = threadIdx.x;
    float wreg[NDIM];
#pragma unroll
    for (int k = 0; k < NDIM; k++) wreg[k] = W[k * HID + tid];
    float bv = bias[tid];
    for (int n0 = blockIdx.x * 16; n0 < NN; n0 += gridDim.x * 16) {
        __syncthreads();
        for (int idx = tid; idx < 16 * NDIM; idx += 96) {
            int nn = n0 + idx / NDIM;
            h_sh[idx] = (nn < NN) ? in[n0 * NDIM + idx] : 0.f;
        }
        __syncthreads();
        float acc[16];
#pragma unroll
        for (int j = 0; j < 16; j++) acc[j] = bv;
#pragma unroll
        for (int k = 0; k < NDIM; k += 4) {
#pragma unroll
            for (int j = 0; j < 16; j++) {
                float4 hv = *(const float4*)&h_sh[j * NDIM + k];
                acc[j] = fmaf(hv.x, wreg[k + 0], acc[j]);
                acc[j] = fmaf(hv.y, wreg[k + 1], acc[j]);
                acc[j] = fmaf(hv.z, wreg[k + 2], acc[j]);
                acc[j] = fmaf(hv.w, wreg[k + 3], acc[j]);
            }
        }
#pragma unroll
        for (int j = 0; j < 16; j++)
            if (n0 + j < NN) out[(n0 + j) * HID + tid] = acc[j];
    }
}

// ---------------- fused lin_l + lin_r, packed f32x2 over K -----------------
__global__ void __launch_bounds__(192) k_lin2(const float* __restrict__ in,
                                              const float* __restrict__ Wl,
                                              const float* __restrict__ bl,
                                              const float* __restrict__ Wr,
                                              const float* __restrict__ br,
                                              float* __restrict__ outl,
                                              float* __restrict__ outr) {
    __shared__ float h_sh[16 * HID];
    int tid = threadIdx.x;
    int col = tid % 96;
    bool isR = tid >= 96;
    const float* W = isR ? Wr : Wl;
    ull wp[48];
#pragma unroll
    for (int kk = 0; kk < 48; kk++) {
        float lo = W[(2 * kk) * HID + col];
        float hi = W[(2 * kk + 1) * HID + col];
        PACK2(wp[kk], lo, hi);
    }
    float bv = isR ? br[col] : bl[col];
    float* out = isR ? outr : outl;

    for (int n0 = blockIdx.x * 16; n0 < NN; n0 += gridDim.x * 16) {
        __syncthreads();
        for (int idx = tid; idx < 16 * HID; idx += 192) {
            int nn = n0 + idx / HID;
            h_sh[idx] = (nn < NN) ? in[n0 * HID + idx] : 0.f;
        }
        __syncthreads();
        ull acc2[16];
#pragma unroll
        for (int j = 0; j < 16; j++) PACK2(acc2[j], bv, 0.f);
#pragma unroll
        for (int kq = 0; kq < 24; kq++) {
#pragma unroll
            for (int j = 0; j < 16; j++) {
                ulonglong2 hv = *(const ulonglong2*)&h_sh[j * HID + 4 * kq];
                FMA2(acc2[j], hv.x, wp[2 * kq], acc2[j]);
                FMA2(acc2[j], hv.y, wp[2 * kq + 1], acc2[j]);
            }
        }
#pragma unroll
        for (int j = 0; j < 16; j++) {
            if (n0 + j < NN) {
                float lo, hi;
                UNPACK2(lo, hi, acc2[j]);
                out[(n0 + j) * HID + col] = lo + hi;
            }
        }
    }
}

// ---------------- fused GATv2 layer (unroll-2 edge pipeline) ---------------
// Warp per node (persistent). Lane owns channels [3*lane, 3*lane+2],
// head = lane/8. Two independent edge chains per iteration; merged online
// softmax update with a single rescale.
__global__ void __launch_bounds__(128) k_layer(const float* __restrict__ We,
                                               const float* __restrict__ att,
                                               const float* __restrict__ cb,
                                               const float* __restrict__ lng,
                                               const float* __restrict__ lnb) {
    int tid = threadIdx.x;
    int lane = tid & 31;
    int w = tid >> 5;
    int c = 3 * lane;

    // lane's 3 We columns as K-pairs (24 packed regs)
    ull w0[8], w1[8], w2[8];
#pragma unroll
    for (int kk = 0; kk < 8; kk++) {
        PACK2(w0[kk], We[(2 * kk) * HID + c],     We[(2 * kk + 1) * HID + c]);
        PACK2(w1[kk], We[(2 * kk) * HID + c + 1], We[(2 * kk + 1) * HID + c + 1]);
        PACK2(w2[kk], We[(2 * kk) * HID + c + 2], We[(2 * kk + 1) * HID + c + 2]);
    }
    float at0 = att[c], at1 = att[c + 1], at2 = att[c + 2];
    float cb0 = cb[c], cb1 = cb[c + 1], cb2 = cb[c + 2];
    float lg0 = lng[c], lg1 = lng[c + 1], lg2 = lng[c + 2];
    float lb0 = lnb[c], lb1 = lnb[c + 1], lb2 = lnb[c + 2];

    for (int n = blockIdx.x * 4 + w; n < NN; n += gridDim.x * 4) {
        int r0 = g_rowptr[n], r1 = g_rowptr[n + 1];
        float xr0 = g_xr[n * HID + c];
        float xr1 = g_xr[n * HID + c + 1];
        float xr2 = g_xr[n * HID + c + 2];

        float mx = -3e38f, s = 0.f;
        float acc0 = 0.f, acc1 = 0.f, acc2v = 0.f;

        const ulonglong2* ep = (const ulonglong2*)(g_eattr_p + (long)r0 * EDIM);
        int i = r0;
        for (; i + 1 < r1; i += 2, ep += 8) {
            // ---- issue both edges' loads up front (MLP) ----
            int sa = g_src_p[i];
            int sb = g_src_p[i + 1];
            ulonglong2 qa0 = ep[0], qa1 = ep[1], qa2 = ep[2], qa3 = ep[3];
            ulonglong2 qb0 = ep[4], qb1 = ep[5], qb2 = ep[6], qb3 = ep[7];
            const float* xap = g_xl + sa * HID;
            const float* xbp = g_xl + sb * HID;
            float xa0 = xap[c], xa1 = xap[c + 1], xa2 = xap[c + 2];
            float xb0 = xbp[c], xb1 = xbp[c + 1], xb2 = xbp[c + 2];

            // ---- edge A GEMM ----
            ull aA[8] = {qa0.x, qa0.y, qa1.x, qa1.y, qa2.x, qa2.y, qa3.x, qa3.y};
            ull pa0, pa1, pa2;
            PACK2(pa0, 0.f, 0.f); PACK2(pa1, 0.f, 0.f); PACK2(pa2, 0.f, 0.f);
#pragma unroll
            for (int kk = 0; kk < 8; kk++) {
                FMA2(pa0, aA[kk], w0[kk], pa0);
                FMA2(pa1, aA[kk], w1[kk], pa1);
                FMA2(pa2, aA[kk], w2[kk], pa2);
            }
            // ---- edge B GEMM (independent chain) ----
            ull aB[8] = {qb0.x, qb0.y, qb1.x, qb1.y, qb2.x, qb2.y, qb3.x, qb3.y};
            ull pb0, pb1, pb2;
            PACK2(pb0, 0.f, 0.f); PACK2(pb1, 0.f, 0.f); PACK2(pb2, 0.f, 0.f);
#pragma unroll
            for (int kk = 0; kk < 8; kk++) {
                FMA2(pb0, aB[kk], w0[kk], pb0);
                FMA2(pb1, aB[kk], w1[kk], pb1);
                FMA2(pb2, aB[kk], w2[kk], pb2);
            }

            float l0, h0f, l1, h1f, l2, h2f;
            UNPACK2(l0, h0f, pa0); UNPACK2(l1, h1f, pa1); UNPACK2(l2, h2f, pa2);
            float ma0 = (l0 + h0f) + (xa0 + xr0);
            float ma1 = (l1 + h1f) + (xa1 + xr1);
            float ma2 = (l2 + h2f) + (xa2 + xr2);
            UNPACK2(l0, h0f, pb0); UNPACK2(l1, h1f, pb1); UNPACK2(l2, h2f, pb2);
            float mb0 = (l0 + h0f) + (xb0 + xr0);
            float mb1 = (l1 + h1f) + (xb1 + xr1);
            float mb2 = (l2 + h2f) + (xb2 + xr2);
            ma0 = fmaxf(ma0, 0.2f * ma0); ma1 = fmaxf(ma1, 0.2f * ma1);
            ma2 = fmaxf(ma2, 0.2f * ma2);
            mb0 = fmaxf(mb0, 0.2f * mb0); mb1 = fmaxf(mb1, 0.2f * mb1);
            mb2 = fmaxf(mb2, 0.2f * mb2);
            float va = ma0 * at0 + ma1 * at1 + ma2 * at2;
            float vb = mb0 * at0 + mb1 * at1 + mb2 * at2;
            // two independent 3-step reduces (pipelined)
            float va4 = __shfl_xor_sync(0xffffffffu, va, 4);
            float vb4 = __shfl_xor_sync(0xffffffffu, vb, 4);
            va += va4; vb += vb4;
            float va2 = __shfl_xor_sync(0xffffffffu, va, 2);
            float vb2 = __shfl_xor_sync(0xffffffffu, vb, 2);
            va += va2; vb += vb2;
            float va1 = __shfl_xor_sync(0xffffffffu, va, 1);
            float vb1 = __shfl_xor_sync(0xffffffffu, vb, 1);
            va += va1; vb += vb1;

            // merged online update (one rescale for both edges)
            float nm = fmaxf(mx, fmaxf(va, vb));
            float sc = __expf(mx - nm);
            float pa = __expf(va - nm);
            float pb = __expf(vb - nm);
            s = fmaf(s, sc, pa + pb);
            acc0  = fmaf(acc0,  sc, fmaf(pa, xa0, pb * xb0));
            acc1  = fmaf(acc1,  sc, fmaf(pa, xa1, pb * xb1));
            acc2v = fmaf(acc2v, sc, fmaf(pa, xa2, pb * xb2));
            mx = nm;
        }
        if (i < r1) {  // tail edge
            int sa = g_src_p[i];
            ulonglong2 qa0 = ep[0], qa1 = ep[1], qa2 = ep[2], qa3 = ep[3];
            const float* xap = g_xl + sa * HID;
            float xa0 = xap[c], xa1 = xap[c + 1], xa2 = xap[c + 2];
            ull aA[8] = {qa0.x, qa0.y, qa1.x, qa1.y, qa2.x, qa2.y, qa3.x, qa3.y};
            ull pa0, pa1, pa2;
            PACK2(pa0, 0.f, 0.f); PACK2(pa1, 0.f, 0.f); PACK2(pa2, 0.f, 0.f);
#pragma unroll
            for (int kk = 0; kk < 8; kk++) {
                FMA2(pa0, aA[kk], w0[kk], pa0);
                FMA2(pa1, aA[kk], w1[kk], pa1);
                FMA2(pa2, aA[kk], w2[kk], pa2);
            }
            float l0, h0f, l1, h1f, l2, h2f;
            UNPACK2(l0, h0f, pa0); UNPACK2(l1, h1f, pa1); UNPACK2(l2, h2f, pa2);
            float ma0 = (l0 + h0f) + (xa0 + xr0);
            float ma1 = (l1 + h1f) + (xa1 + xr1);
            float ma2 = (l2 + h2f) + (xa2 + xr2);
            ma0 = fmaxf(ma0, 0.2f * ma0); ma1 = fmaxf(ma1, 0.2f * ma1);
            ma2 = fmaxf(ma2, 0.2f * ma2);
            float va = ma0 * at0 + ma1 * at1 + ma2 * at2;
            va += __shfl_xor_sync(0xffffffffu, va, 4);
            va += __shfl_xor_sync(0xffffffffu, va, 2);
            va += __shfl_xor_sync(0xffffffffu, va, 1);
            float nm = fmaxf(mx, va);
            float sc = __expf(mx - nm);
            float pa = __expf(va - nm);
            s = fmaf(s, sc, pa);
            acc0  = fmaf(acc0,  sc, pa * xa0);
            acc1  = fmaf(acc1,  sc, pa * xa1);
            acc2v = fmaf(acc2v, sc, pa * xa2);
            mx = nm;
        }

        float inv = 1.f / (s + 1e-16f);
        float h0 = g_h[n * HID + c]     + acc0  * inv + cb0;
        float h1 = g_h[n * HID + c + 1] + acc1  * inv + cb1;
        float h2 = g_h[n * HID + c + 2] + acc2v * inv + cb2;
        float sm = h0 + h1 + h2;
#pragma unroll
        for (int off = 16; off; off >>= 1) sm += __shfl_xor_sync(0xffffffffu, sm, off);
        float mu = sm * (1.f / 96.f);
        float d0 = h0 - mu, d1 = h1 - mu, d2 = h2 - mu;
        float vv = d0 * d0 + d1 * d1 + d2 * d2;
#pragma unroll
        for (int off = 16; off; off >>= 1) vv += __shfl_xor_sync(0xffffffffu, vv, off);
        float rs = rsqrtf(vv * (1.f / 96.f) + 1e-5f);
        g_h[n * HID + c]     = d0 * rs * lg0 + lb0;
        g_h[n * HID + c + 1] = d1 * rs * lg1 + lb1;
        g_h[n * HID + c + 2] = d2 * rs * lg2 + lb2;
    }
}

// ---------------- MLP head -------------------------------------------------
__global__ void __launch_bounds__(128) k_head(const float* __restrict__ w1,
                                              const float* __restrict__ b1,
                                              const float* __restrict__ w2,
                                              const float* __restrict__ b2,
                                              float* __restrict__ out) {
    __shared__ float w1s[HID * 48];
    __shared__ float b1s[48];
    __shared__ float w2s[48];
    int tid = threadIdx.x;
    for (int i = tid; i < HID * 48; i += 128) w1s[i] = w1[i];
    if (tid < 48) { b1s[tid] = b1[tid]; w2s[tid] = w2[tid]; }
    __syncthreads();
    int node = blockIdx.x * 128 + tid;
    if (node >= NN) return;

    float hreg[HID];
#pragma unroll
    for (int k = 0; k < HID; k += 4) {
        float4 v = *(const float4*)&g_h[node * HID + k];
        hreg[k] = v.x; hreg[k + 1] = v.y; hreg[k + 2] = v.z; hreg[k + 3] = v.w;
    }
    float y = 0.f;
#pragma unroll 2
    for (int j = 0; j < 48; j += 4) {
        float a0 = b1s[j], a1 = b1s[j + 1], a2 = b1s[j + 2], a3 = b1s[j + 3];
#pragma unroll
        for (int k = 0; k < HID; k++) {
            float4 wv = *(const float4*)&w1s[k * 48 + j];
            a0 = fmaf(hreg[k], wv.x, a0);
            a1 = fmaf(hreg[k], wv.y, a1);
            a2 = fmaf(hreg[k], wv.z, a2);
            a3 = fmaf(hreg[k], wv.w, a3);
        }
        float g0 = 0.5f * a0 * (1.f + erff(a0 * 0.70710678118654752f));
        float g1 = 0.5f * a1 * (1.f + erff(a1 * 0.70710678118654752f));
        float g2 = 0.5f * a2 * (1.f + erff(a2 * 0.70710678118654752f));
        float g3 = 0.5f * a3 * (1.f + erff(a3 * 0.70710678118654752f));
        y = fmaf(g0, w2s[j], y);
        y = fmaf(g1, w2s[j + 1], y);
        y = fmaf(g2, w2s[j + 2], y);
        y = fmaf(g3, w2s[j + 3], y);
    }
    out[node] = y + b2[0];
}

// ---------------- launch ---------------------------------------------------
extern "C" void kernel_launch(void* const* d_in, const int* in_sizes, int n_in,
                              void* d_out, int out_size) {
    const float* x      = (const float*)d_in[0];
    const int*   ei     = (const int*)d_in[1];
    const float* eattr  = (const float*)d_in[2];
    const float* proj_w = (const float*)d_in[3];
    const float* proj_b = (const float*)d_in[4];
    const float* ll_w   = (const float*)d_in[5];
    const float* ll_b   = (const float*)d_in[6];
    const float* lr_w   = (const float*)d_in[7];
    const float* lr_b   = (const float*)d_in[8];
    const float* le_w   = (const float*)d_in[9];
    const float* att    = (const float*)d_in[10];
    const float* cb     = (const float*)d_in[11];
    const float* lng    = (const float*)d_in[12];
    const float* lnb    = (const float*)d_in[13];
    const float* hw1    = (const float*)d_in[14];
    const float* hb1    = (const float*)d_in[15];
    const float* hw2    = (const float*)d_in[16];
    const float* hb2    = (const float*)d_in[17];
    float* out = (float*)d_out;

    const int* src = ei;
    const int* dst = ei + EE;

    float *ph, *pxl, *pxr;
    cudaGetSymbolAddress((void**)&ph,  g_h);
    cudaGetSymbolAddress((void**)&pxl, g_xl);
    cudaGetSymbolAddress((void**)&pxr, g_xr);

    // CSR build + edge permutation (once per call)
    k_zero<<<(NN + 256) / 256, 256>>>();
    k_count<<<(EE + 255) / 256, 256>>>(dst);
    k_scan<<<1, 1024>>>();
    k_fill<<<(EE + 255) / 256, 256>>>(src, dst);
    k_perm<<<(EE + 255) / 256, 256>>>(eattr);

    // input projection (persistent)
    k_proj<<<592, 96>>>(x, proj_w, proj_b, ph);

    for (int l = 0; l < 3; l++) {
        k_lin2<<<592, 192>>>(ph, ll_w + l * HID * HID, ll_b + l * HID,
                             lr_w + l * HID * HID, lr_b + l * HID, pxl, pxr);
        k_layer<<<1184, 128>>>(le_w + l * EDIM * HID, att + l * HID,
                               cb + l * HID, lng + l * HID, lnb + l * HID);
    }

    k_head<<<(NN + 127) / 128, 128>>>(hw1, hb1, hw2, hb2, out);
}